// round 15
// baseline (speedup 1.0000x reference)
#include <cuda_runtime.h>
#include <cuda_bf16.h>

#define NV 10000
#define BB 8
#define NE 2000000
#define NB (NV * BB)

// Edge-pass geometry: 64 edges per warp, 31250 warps exactly -> no bounds checks.
#define TBP 320                       // threads per pass CTA (10 warps)
#define NBLK (NE / 64 / (TBP / 32))   // 3125 CTAs

#define NODE_BLOCKS ((NV + 31) / 32)  // 313: each block = 32 nodes x 8 batches

// Node tables in [N, B] layout: each node's 8 batch values = one 32B chunk.
__device__ float g_fx[NB];        // tanh(x)
__device__ float g_err[NB];       // init x; pass1 reds -w*fx -> becomes x-pred
__device__ float g_aggr[NB];      // scatter accumulator (by src)

// ---------------------------------------------------------------------------
// prep: block = 32 nodes x 8 batches. Coalesced values reads in (b,n) order,
// smem transpose, coalesced linear table writes in i = n*8+b order.
__global__ __launch_bounds__(256) void prep_kernel(
        const float* __restrict__ values) {
    cudaTriggerProgrammaticLaunchCompletion();
    __shared__ float sx[32][9];            // padded: conflict-free transpose
    int tid = threadIdx.x;
    int n0  = blockIdx.x * 32;

    int r = tid & 31, b = tid >> 5;        // read order: (b, n0+r)
    int n = n0 + r;
    float x = (n < NV) ? __ldg(values + b * NV + n) : 0.0f;
    sx[r][b] = x;
    __syncthreads();

    int rr = tid >> 3, bb = tid & 7;       // write order: i = (n0+rr)*8 + bb
    if (n0 + rr < NV) {
        int i = n0 * 8 + tid;
        float xt = sx[rr][bb];
        g_fx[i]   = tanhf(xt);
        g_err[i]  = xt;      // err starts at x; pass1 subtracts pred via red
        g_aggr[i] = 0.0f;
    }
}

// ---------------------------------------------------------------------------
__device__ __forceinline__ void red_add_v4(float* p, float4 v) {
    asm volatile("red.global.add.v4.f32 [%0], {%1, %2, %3, %4};"
                 :: "l"(p), "f"(v.x), "f"(v.y), "f"(v.z), "f"(v.w));
}

// ---------------------------------------------------------------------------
// idx dtype self-sniff (inputs only, PDL-safe): indices < 10000, so int64
// means odd 32-bit words are all 0. P(false positive for int32) ~ 1e-16.
__device__ __forceinline__ int sniff_idx64(const void* ei) {
    const unsigned int* w = (const unsigned int*)ei;
    return (w[1] == 0u) & (w[3] == 0u) & (w[5] == 0u) & (w[7] == 0u);
}

// load 4 (s,t,w) triples for this lane's edge slots; pure input reads.
__device__ __forceinline__ void load_edges(
        const void* ei, const float* w, int base, int idx64,
        int s[4], int t[4], float we[4]) {
    #pragma unroll
    for (int k = 0; k < 4; k++) {
        int e = base + k * 16;
        if (idx64) {
            s[k] = (int)__ldg((const long long*)ei + e);
            t[k] = (int)__ldg((const long long*)ei + NE + e);
        } else {
            s[k] = __ldg((const int*)ei + e);
            t[k] = __ldg((const int*)ei + NE + e);
        }
        we[k] = __ldg(w + e);
    }
}

// ===========================================================================
// Edge passes: 2 lanes per edge (confirmed at the L1tex line floor).
// Lane pair (2k, 2k+1) owns one edge; parity p = lane&1 selects which 16B
// half of the node's 32B batch-chunk this lane handles. One LDG.128 gathers
// (adjacent lanes -> same 32B chunk -> 1 line/edge); one full-warp red.v4
// scatters. Each warp covers 64 contiguous edges.
//
// PDL chain:  prep --(entry trig)--> pass1 --(entry trig)--> pass2
//             pass2 --(POST-sync trig)--> final
// BOTH passes read only raw inputs (edge_index, weights) in their prologue,
// BEFORE their grid sync -> the entire edge stream of pass2 overlaps pass1's
// execution; only gather+red remain on the post-sync critical path.
// ===========================================================================

// pass1: err[tgt] -= w * fx[src]
__global__ __launch_bounds__(TBP) void pass1_kernel(
        const void* __restrict__ ei, const float* __restrict__ w) {
    cudaTriggerProgrammaticLaunchCompletion();
    int lane = threadIdx.x & 31;
    int p    = lane & 1;        // 16B half selector
    int eo   = lane >> 1;       // edge slot within warp-step (0..15)
    int warp = blockIdx.x * (TBP / 32) + (threadIdx.x >> 5);
    int base = warp * 64 + eo;

    int idx64 = sniff_idx64(ei);
    int   s[4], t[4];
    float we[4];
    float4 v[4];
    load_edges(ei, w, base, idx64, s, t, we);   // input-only, overlaps prep

    cudaGridDependencySynchronize();   // wait for prep's fx/err tables

    #pragma unroll
    for (int k = 0; k < 4; k++) {
        v[k] = __ldg(reinterpret_cast<const float4*>(g_fx) + s[k] * 2 + p);
    }
    #pragma unroll
    for (int k = 0; k < 4; k++) {
        float wk = -we[k];             // negated: err accumulates x - pred
        red_add_v4(g_err + (size_t)t[k] * 8 + p * 4,
                   make_float4(wk * v[k].x, wk * v[k].y,
                               wk * v[k].z, wk * v[k].w));
    }
}

// ---------------------------------------------------------------------------
// pass2: aggr[src] += w * err[tgt].  Edge-stream prologue is input-only and
// runs BEFORE the sync -> fully overlapped with pass1. Trigger AFTER sync:
// final's blocks then launch only once pass1 (hence prep) is complete.
__global__ __launch_bounds__(TBP) void pass2_kernel(
        const void* __restrict__ ei, const float* __restrict__ w) {
    int lane = threadIdx.x & 31;
    int p    = lane & 1;
    int eo   = lane >> 1;
    int warp = blockIdx.x * (TBP / 32) + (threadIdx.x >> 5);
    int base = warp * 64 + eo;

    int idx64 = sniff_idx64(ei);
    int   s[4], t[4];
    float we[4];
    float4 v[4];
    load_edges(ei, w, base, idx64, s, t, we);   // input-only, overlaps pass1

    cudaGridDependencySynchronize();   // wait for pass1 (err complete)
    cudaTriggerProgrammaticLaunchCompletion();

    #pragma unroll
    for (int k = 0; k < 4; k++) {
        v[k] = __ldg(reinterpret_cast<const float4*>(g_err) + t[k] * 2 + p);
    }
    #pragma unroll
    for (int k = 0; k < 4; k++) {
        float wk = we[k];
        red_add_v4(g_aggr + (size_t)s[k] * 8 + p * 4,
                   make_float4(wk * v[k].x, wk * v[k].y,
                               wk * v[k].z, wk * v[k].w));
    }
}

// ---------------------------------------------------------------------------
// final: block = 32 nodes x 8 batches.
// Phase A (pre-sync: pass1 complete by PDL chain): coalesced i-order reads of
// fx/err; prefetch x in output order. Post-sync: coalesced aggr read, dx,
// smem transpose. Phase B: fully coalesced writes of all 3 output streams at
// o = b*NV + n; pred = x - err computed there.
// out layout: [3, B*N], inner [B, N].
__global__ __launch_bounds__(256) void final_kernel(
        const float* __restrict__ values, float* __restrict__ out) {
    __shared__ float ser[32][9];
    __shared__ float sdx[32][9];
    int tid = threadIdx.x;
    int n0  = blockIdx.x * 32;

    int rr = tid >> 3, bb = tid & 7;       // table order: i = (n0+rr)*8 + bb
    int i  = n0 * 8 + tid;
    bool okA = (n0 + rr < NV);
    int ic = okA ? i : 0;
    float fx = g_fx[ic];
    float er = g_err[ic];

    int rB = tid & 31, bB = tid >> 5;      // output order: o = bB*NV + n0+rB
    int nB = n0 + rB;
    bool okB = (nB < NV);
    int o = bB * NV + (okB ? nB : 0);
    float x = __ldg(values + o);           // input: no ordering needed

    cudaGridDependencySynchronize();       // wait for pass2 (aggr only)

    if (okA) {
        float ag = g_aggr[i];
        ser[rr][bb] = er;
        sdx[rr][bb] = er - (1.0f - fx * fx) * ag;
    }
    __syncthreads();

    if (okB) {
        float er_t = ser[rB][bB];
        out[o]          = x - er_t;        // pred
        out[NB + o]     = er_t;            // err
        out[2 * NB + o] = sdx[rB][bB];     // dx
    }
}

// ---------------------------------------------------------------------------
extern "C" void kernel_launch(void* const* d_in, const int* in_sizes, int n_in,
                              void* d_out, int out_size) {
    const float* values  = (const float*)d_in[0];
    const float* weights = (const float*)d_in[1];
    const void*  ei      = (const void*)d_in[2];
    float* out = (float*)d_out;

    prep_kernel<<<NODE_BLOCKS, 256>>>(values);

    cudaLaunchAttribute attr;
    attr.id = cudaLaunchAttributeProgrammaticStreamSerialization;
    attr.val.programmaticStreamSerializationAllowed = 1;

    cudaLaunchConfig_t cfg = {};
    cfg.attrs = &attr;
    cfg.numAttrs = 1;
    cfg.stream = 0;

    cfg.gridDim = dim3(NBLK);
    cfg.blockDim = dim3(TBP);
    cudaLaunchKernelEx(&cfg, pass1_kernel, (const void*)ei, weights);
    cudaLaunchKernelEx(&cfg, pass2_kernel, (const void*)ei, weights);

    cfg.gridDim = dim3(NODE_BLOCKS);
    cfg.blockDim = dim3(256);
    cudaLaunchKernelEx(&cfg, final_kernel, values, out);
}